// round 12
// baseline (speedup 1.0000x reference)
#include <cuda_runtime.h>

#define DMODEL     1024
#define NEXP       8
#define TOKENS_TOT 32768
#define TPB        128
#define WARPS      4                 // per CTA
#define TPW        16                // tokens per warp
#define TPG        4                 // tokens per inner group
#define NGRP       (TPW / TPG)       // 4
#define NBLOCKS    (TOKENS_TOT / (WARPS * TPW))   // 512

typedef unsigned long long ull;

// ---------- packed fp32x2 FMA (sm_103a) ----------
__device__ __forceinline__ ull ffma2(ull a, ull b, ull c) {
    ull d;
    asm("fma.rn.f32x2 %0, %1, %2, %3;" : "=l"(d) : "l"(a), "l"(b), "l"(c));
    return d;
}
__device__ __forceinline__ void unpack2(ull v, float& lo, float& hi) {
    asm("mov.b64 {%0, %1}, %2;" : "=f"(lo), "=f"(hi) : "l"(v));
}

// Warp-autonomous gating (R10 mainloop). Lane owns dims
// {c*128 + lane*4 .. +4 | c=0..7}; a warp spans all 1024 dims of a token.
// W staged once in SMEM (32 KB), re-read per chunk amortized over 4 tokens.
// Group tail = interleaved 4-token butterfly only (~200 cyc); the top-2 +
// softmax epilogue is DEFERRED to kernel end and runs one-token-per-lane,
// so the mainloop never drains the memory pipe for epilogue chains.
__global__ void __launch_bounds__(TPB, 4)
gating_kernel(const float* __restrict__ x, const float* __restrict__ W,
              const float* __restrict__ b, float* __restrict__ out_w,
              float* __restrict__ out_i, int write_idx)
{
    __shared__ ulonglong2 Ws[NEXP * 256];      // 8 x 1024 floats = 32 KB
    __shared__ float Ls[WARPS][TPW][9];        // biased logits, pad 9 (no bank conflicts)

    const int tid  = threadIdx.x;
    const int lane = tid & 31;
    const int wid  = tid >> 5;

    // Stage W: 2048 x 16B / 128 threads = 16 each.
    {
        const ulonglong2* Wv = (const ulonglong2*)W;
#pragma unroll
        for (int i = 0; i < 16; i++)
            Ws[tid + i * TPB] = Wv[tid + i * TPB];
    }
    __syncthreads();   // the only block barrier in the kernel

    const int   elane = (lane >> 2) & 7;
    const float bval  = b[elane];

    const int t0 = (blockIdx.x * WARPS + wid) * TPW;
    // token row = 256 x 16B units; chunk c -> unit c*32 + lane
    const ulonglong2* xp = (const ulonglong2*)x + (size_t)t0 * 256 + lane;

    // Prologue: group 0, chunk 0 for 4 tokens (depth-1 prefetch).
    ulonglong2 xb[TPG];
#pragma unroll
    for (int t = 0; t < TPG; t++) xb[t] = xp[t * 256];

#pragma unroll 1
    for (int g = 0; g < NGRP; g++) {
        ull acc[NEXP][TPG];
#pragma unroll
        for (int e = 0; e < NEXP; e++)
#pragma unroll
            for (int t = 0; t < TPG; t++) acc[e][t] = 0ull;

        const int gbase = g * TPG * 256;

#pragma unroll
        for (int c = 0; c < 8; c++) {
            ull xlo[TPG], xhi[TPG];
#pragma unroll
            for (int t = 0; t < TPG; t++) { xlo[t] = xb[t].x; xhi[t] = xb[t].y; }

            // Prefetch next chunk (or next group's chunk 0).
            if (c < 7) {
                const int o = gbase + (c + 1) * 32;
#pragma unroll
                for (int t = 0; t < TPG; t++) xb[t] = xp[o + t * 256];
            } else if (g < NGRP - 1) {
                const int o = (g + 1) * TPG * 256;
#pragma unroll
                for (int t = 0; t < TPG; t++) xb[t] = xp[o + t * 256];
            }

            // W for this chunk, 4 experts at a time.
            const ulonglong2* wrow = Ws + c * 32 + lane;
#pragma unroll
            for (int eb = 0; eb < NEXP; eb += 4) {
                ulonglong2 w0 = wrow[(eb + 0) * 256];
                ulonglong2 w1 = wrow[(eb + 1) * 256];
                ulonglong2 w2 = wrow[(eb + 2) * 256];
                ulonglong2 w3 = wrow[(eb + 3) * 256];
#pragma unroll
                for (int t = 0; t < TPG; t++) {
                    acc[eb + 0][t] = ffma2(xhi[t], w0.y, ffma2(xlo[t], w0.x, acc[eb + 0][t]));
                    acc[eb + 1][t] = ffma2(xhi[t], w1.y, ffma2(xlo[t], w1.x, acc[eb + 1][t]));
                    acc[eb + 2][t] = ffma2(xhi[t], w2.y, ffma2(xlo[t], w2.x, acc[eb + 2][t]));
                    acc[eb + 3][t] = ffma2(xhi[t], w3.y, ffma2(xlo[t], w3.x, acc[eb + 3][t]));
                }
            }
        }

        // Interleaved 4-token butterfly: experts over lane bits 4,3,2; dims
        // over bits 1,0. Four independent chains overlap (~200 cyc total).
        float s[TPG][NEXP];
#pragma unroll
        for (int t = 0; t < TPG; t++)
#pragma unroll
            for (int e = 0; e < NEXP; e++) {
                float lo, hi; unpack2(acc[e][t], lo, hi);
                s[t][e] = lo + hi;
            }

        const bool h16 = (lane & 16) != 0;
#pragma unroll
        for (int v = 0; v < 4; v++)
#pragma unroll
            for (int t = 0; t < TPG; t++) {
                float d = __shfl_xor_sync(~0u, h16 ? s[t][v] : s[t][v + 4], 16);
                s[t][v] = (h16 ? s[t][v + 4] : s[t][v]) + d;
            }
        const bool h8 = (lane & 8) != 0;
#pragma unroll
        for (int v = 0; v < 2; v++)
#pragma unroll
            for (int t = 0; t < TPG; t++) {
                float d = __shfl_xor_sync(~0u, h8 ? s[t][v] : s[t][v + 2], 8);
                s[t][v] = (h8 ? s[t][v + 2] : s[t][v]) + d;
            }
        const bool h4 = (lane & 4) != 0;
#pragma unroll
        for (int t = 0; t < TPG; t++) {
            float d = __shfl_xor_sync(~0u, h4 ? s[t][0] : s[t][1], 4);
            s[t][0] = (h4 ? s[t][1] : s[t][0]) + d;
        }
#pragma unroll
        for (int t = 0; t < TPG; t++) {
            float r = s[t][0];
            r += __shfl_xor_sync(~0u, r, 2);
            r += __shfl_xor_sync(~0u, r, 1);
            s[t][0] = r;
        }

        // Park biased logits; epilogue deferred to kernel end.
        if ((lane & 3) == 0)
#pragma unroll
            for (int t = 0; t < TPG; t++)
                Ls[wid][g * TPG + t][elane] = s[t][0] + bval;
    }

    __syncwarp();

    // Final epilogue: lane l (<16) owns token t0+l. Serial two-max scan with
    // first-occurrence tie-break == lax.top_k semantics.
    if (lane < TPW) {
        const float* Lrow = Ls[wid][lane];
        float v[NEXP];
#pragma unroll
        for (int e = 0; e < NEXP; e++) v[e] = Lrow[e];

        float v1 = v[0]; int i1 = 0;
        float v2 = __int_as_float(0xff800000); int i2 = 0;
#pragma unroll
        for (int e = 1; e < NEXP; e++) {
            if (v[e] > v1)      { v2 = v1; i2 = i1; v1 = v[e]; i1 = e; }
            else if (v[e] > v2) { v2 = v[e]; i2 = e; }
        }

        const float tt  = __expf(v2 - v1);    // v2 <= v1 -> (0,1]
        const float inv = 1.0f / (1.0f + tt);
        const float w1  = inv, w2 = tt * inv;

        const int token = t0 + lane;
        float4 o0, o1;
        o0.x = (i1 == 0) ? w1 : ((i2 == 0) ? w2 : 0.0f);
        o0.y = (i1 == 1) ? w1 : ((i2 == 1) ? w2 : 0.0f);
        o0.z = (i1 == 2) ? w1 : ((i2 == 2) ? w2 : 0.0f);
        o0.w = (i1 == 3) ? w1 : ((i2 == 3) ? w2 : 0.0f);
        o1.x = (i1 == 4) ? w1 : ((i2 == 4) ? w2 : 0.0f);
        o1.y = (i1 == 5) ? w1 : ((i2 == 5) ? w2 : 0.0f);
        o1.z = (i1 == 6) ? w1 : ((i2 == 6) ? w2 : 0.0f);
        o1.w = (i1 == 7) ? w1 : ((i2 == 7) ? w2 : 0.0f);
        float4* op = (float4*)(out_w + token * 8);
        op[0] = o0;
        op[1] = o1;

        if (write_idx)
            *(float2*)(out_i + token * 2) = make_float2((float)i1, (float)i2);
    }
}

extern "C" void kernel_launch(void* const* d_in, const int* in_sizes, int n_in,
                              void* d_out, int out_size)
{
    const float* x = nullptr; const float* W = nullptr; const float* b = nullptr;
    for (int i = 0; i < n_in; i++) {
        if (in_sizes[i] == NEXP)                b = (const float*)d_in[i];
        else if (in_sizes[i] == NEXP * DMODEL)  W = (const float*)d_in[i];
        else                                    x = (const float*)d_in[i];
    }

    float* ow = (float*)d_out;                       // weights: [B,S,E] f32
    float* oi = ow + (size_t)TOKENS_TOT * NEXP;      // indices (as f32): [B,S,2]
    const int need = TOKENS_TOT * NEXP + TOKENS_TOT * 2;
    const int write_idx = (out_size >= need) ? 1 : 0;

    gating_kernel<<<NBLOCKS, TPB>>>(x, W, b, ow, oi, write_idx);
}

// round 13
// speedup vs baseline: 1.0092x; 1.0092x over previous
#include <cuda_runtime.h>

#define DMODEL     1024
#define NEXP       8
#define TOKENS_TOT 32768
#define TPB        128
#define WARPS      4                 // per CTA
#define TPW        16                // tokens per warp
#define TPG        4                 // tokens per inner group
#define NGRP       (TPW / TPG)       // 4
#define NBLOCKS    (TOKENS_TOT / (WARPS * TPW))   // 512

typedef unsigned long long ull;

// ---------- packed fp32x2 FMA (sm_103a) ----------
__device__ __forceinline__ ull ffma2(ull a, ull b, ull c) {
    ull d;
    asm("fma.rn.f32x2 %0, %1, %2, %3;" : "=l"(d) : "l"(a), "l"(b), "l"(c));
    return d;
}
__device__ __forceinline__ void unpack2(ull v, float& lo, float& hi) {
    asm("mov.b64 {%0, %1}, %2;" : "=f"(lo), "=f"(hi) : "l"(v));
}

// Warp-autonomous gating: R10 mainloop + sequential per-token butterfly,
// with the ONLY change being the epilogue: instead of 4 REDUX chains + expf
// per token inside the group tail, each token's biased logit is parked in a
// padded smem slab and a single deferred per-lane epilogue (token-per-lane)
// runs once at kernel end. Keeps register pressure identical to R10.
__global__ void __launch_bounds__(TPB, 4)
gating_kernel(const float* __restrict__ x, const float* __restrict__ W,
              const float* __restrict__ b, float* __restrict__ out_w,
              float* __restrict__ out_i, int write_idx)
{
    __shared__ ulonglong2 Ws[NEXP * 256];   // 8 x 1024 floats = 32 KB
    __shared__ float Ls[WARPS][TPW][9];     // biased logits; pad 9 => no bank conflicts

    const int tid  = threadIdx.x;
    const int lane = tid & 31;
    const int wid  = tid >> 5;

    // Stage W: 2048 x 16B / 128 threads = 16 each.
    {
        const ulonglong2* Wv = (const ulonglong2*)W;
#pragma unroll
        for (int i = 0; i < 16; i++)
            Ws[tid + i * TPB] = Wv[tid + i * TPB];
    }
    __syncthreads();   // the only block barrier in the kernel

    const int   elane = (lane >> 2) & 7;
    const float bval  = b[elane];

    const int t0 = (blockIdx.x * WARPS + wid) * TPW;
    // token row = 256 x 16B units; chunk c -> unit c*32 + lane
    const ulonglong2* xp = (const ulonglong2*)x + (size_t)t0 * 256 + lane;

    // Prologue: group 0, chunk 0 for 4 tokens (depth-1 prefetch).
    ulonglong2 xb[TPG];
#pragma unroll
    for (int t = 0; t < TPG; t++) xb[t] = xp[t * 256];

#pragma unroll 1
    for (int g = 0; g < NGRP; g++) {
        ull acc[NEXP][TPG];
#pragma unroll
        for (int e = 0; e < NEXP; e++)
#pragma unroll
            for (int t = 0; t < TPG; t++) acc[e][t] = 0ull;

        const int gbase = g * TPG * 256;

#pragma unroll
        for (int c = 0; c < 8; c++) {
            ull xlo[TPG], xhi[TPG];
#pragma unroll
            for (int t = 0; t < TPG; t++) { xlo[t] = xb[t].x; xhi[t] = xb[t].y; }

            // Prefetch next chunk (or next group's chunk 0).
            if (c < 7) {
                const int o = gbase + (c + 1) * 32;
#pragma unroll
                for (int t = 0; t < TPG; t++) xb[t] = xp[o + t * 256];
            } else if (g < NGRP - 1) {
                const int o = (g + 1) * TPG * 256;
#pragma unroll
                for (int t = 0; t < TPG; t++) xb[t] = xp[o + t * 256];
            }

            // W for this chunk, 4 experts at a time.
            const ulonglong2* wrow = Ws + c * 32 + lane;
#pragma unroll
            for (int eb = 0; eb < NEXP; eb += 4) {
                ulonglong2 w0 = wrow[(eb + 0) * 256];
                ulonglong2 w1 = wrow[(eb + 1) * 256];
                ulonglong2 w2 = wrow[(eb + 2) * 256];
                ulonglong2 w3 = wrow[(eb + 3) * 256];
#pragma unroll
                for (int t = 0; t < TPG; t++) {
                    acc[eb + 0][t] = ffma2(xhi[t], w0.y, ffma2(xlo[t], w0.x, acc[eb + 0][t]));
                    acc[eb + 1][t] = ffma2(xhi[t], w1.y, ffma2(xlo[t], w1.x, acc[eb + 1][t]));
                    acc[eb + 2][t] = ffma2(xhi[t], w2.y, ffma2(xlo[t], w2.x, acc[eb + 2][t]));
                    acc[eb + 3][t] = ffma2(xhi[t], w3.y, ffma2(xlo[t], w3.x, acc[eb + 3][t]));
                }
            }
        }

        // Per-token sequential butterfly (exactly R10): experts over lane
        // bits 4,3,2; dims over bits 1,0. Then park the biased logit.
#pragma unroll
        for (int t = 0; t < TPG; t++) {
            float s[NEXP];
#pragma unroll
            for (int e = 0; e < NEXP; e++) {
                float lo, hi; unpack2(acc[e][t], lo, hi);
                s[e] = lo + hi;
            }

            const bool h16 = (lane & 16) != 0;
#pragma unroll
            for (int v = 0; v < 4; v++) {
                float d = __shfl_xor_sync(~0u, h16 ? s[v] : s[v + 4], 16);
                s[v] = (h16 ? s[v + 4] : s[v]) + d;
            }
            const bool h8 = (lane & 8) != 0;
#pragma unroll
            for (int v = 0; v < 2; v++) {
                float d = __shfl_xor_sync(~0u, h8 ? s[v] : s[v + 2], 8);
                s[v] = (h8 ? s[v + 2] : s[v]) + d;
            }
            const bool h4 = (lane & 4) != 0;
            {
                float d = __shfl_xor_sync(~0u, h4 ? s[0] : s[1], 4);
                s[0] = (h4 ? s[1] : s[0]) + d;
            }
            float r = s[0];
            r += __shfl_xor_sync(~0u, r, 2);
            r += __shfl_xor_sync(~0u, r, 1);

            // Park biased logit for expert `elane` (one STS from 8 lanes).
            if ((lane & 3) == 0)
                Ls[wid][g * TPG + t][elane] = r + bval;
        }
    }

    __syncwarp();

    // Deferred epilogue: lane l (<16) owns token t0+l. Serial two-max scan,
    // first-occurrence tie-break == lax.top_k semantics.
    if (lane < TPW) {
        const float* Lrow = Ls[wid][lane];
        float v[NEXP];
#pragma unroll
        for (int e = 0; e < NEXP; e++) v[e] = Lrow[e];

        float v1 = v[0]; int i1 = 0;
        float v2 = __int_as_float(0xff800000); int i2 = 0;
#pragma unroll
        for (int e = 1; e < NEXP; e++) {
            if (v[e] > v1)      { v2 = v1; i2 = i1; v1 = v[e]; i1 = e; }
            else if (v[e] > v2) { v2 = v[e]; i2 = e; }
        }

        const float tt  = __expf(v2 - v1);    // v2 <= v1 -> (0,1]
        const float inv = 1.0f / (1.0f + tt);
        const float w1  = inv, w2 = tt * inv;

        const int token = t0 + lane;
        float4 o0, o1;
        o0.x = (i1 == 0) ? w1 : ((i2 == 0) ? w2 : 0.0f);
        o0.y = (i1 == 1) ? w1 : ((i2 == 1) ? w2 : 0.0f);
        o0.z = (i1 == 2) ? w1 : ((i2 == 2) ? w2 : 0.0f);
        o0.w = (i1 == 3) ? w1 : ((i2 == 3) ? w2 : 0.0f);
        o1.x = (i1 == 4) ? w1 : ((i2 == 4) ? w2 : 0.0f);
        o1.y = (i1 == 5) ? w1 : ((i2 == 5) ? w2 : 0.0f);
        o1.z = (i1 == 6) ? w1 : ((i2 == 6) ? w2 : 0.0f);
        o1.w = (i1 == 7) ? w1 : ((i2 == 7) ? w2 : 0.0f);
        float4* op = (float4*)(out_w + token * 8);
        op[0] = o0;
        op[1] = o1;

        if (write_idx)
            *(float2*)(out_i + token * 2) = make_float2((float)i1, (float)i2);
    }
}

extern "C" void kernel_launch(void* const* d_in, const int* in_sizes, int n_in,
                              void* d_out, int out_size)
{
    const float* x = nullptr; const float* W = nullptr; const float* b = nullptr;
    for (int i = 0; i < n_in; i++) {
        if (in_sizes[i] == NEXP)                b = (const float*)d_in[i];
        else if (in_sizes[i] == NEXP * DMODEL)  W = (const float*)d_in[i];
        else                                    x = (const float*)d_in[i];
    }

    float* ow = (float*)d_out;                       // weights: [B,S,E] f32
    float* oi = ow + (size_t)TOKENS_TOT * NEXP;      // indices (as f32): [B,S,2]
    const int need = TOKENS_TOT * NEXP + TOKENS_TOT * 2;
    const int write_idx = (out_size >= need) ? 1 : 0;

    gating_kernel<<<NBLOCKS, TPB>>>(x, W, b, ow, oi, write_idx);
}

// round 14
// speedup vs baseline: 2.0873x; 2.0682x over previous
#include <cuda_runtime.h>

#define DMODEL     1024
#define NEXP       8
#define TOKENS_TOT 32768
#define TPB        128
#define WARPS      4            // per CTA
#define TPW        16           // tokens per warp
#define TPG        4            // tokens per group (inner batch)
#define NGRP       (TPW / TPG)  // 4
#define NCHUNK     (NGRP * 8)   // 32 flat chunk steps per warp
#define NBLOCKS    (TOKENS_TOT / (WARPS * TPW))   // 512

typedef unsigned long long ull;

// ---------- packed fp32x2 helpers (sm_103a FFMA2 path) ----------
__device__ __forceinline__ ull pack2(float lo, float hi) {
    ull d;
    asm("mov.b64 %0, {%1, %2};" : "=l"(d) : "f"(lo), "f"(hi));
    return d;
}
__device__ __forceinline__ void unpack2(ull v, float& lo, float& hi) {
    asm("mov.b64 {%0, %1}, %2;" : "=f"(lo), "=f"(hi) : "l"(v));
}
__device__ __forceinline__ ull ffma2(ull a, ull b, ull c) {
    ull d;
    asm("fma.rn.f32x2 %0, %1, %2, %3;" : "=l"(d) : "l"(a), "l"(b), "l"(c));
    return d;
}

// ---------- integer warp redux (f32 redux does NOT exist on sm_103) ----------
__device__ __forceinline__ unsigned redux_max_u32(unsigned v) {
    unsigned r;
    asm volatile("redux.sync.max.u32 %0, %1, 0xffffffff;" : "=r"(r) : "r"(v));
    return r;
}
__device__ __forceinline__ unsigned redux_min_u32(unsigned v) {
    unsigned r;
    asm volatile("redux.sync.min.u32 %0, %1, 0xffffffff;" : "=r"(r) : "r"(v));
    return r;
}

// Order-preserving float <-> u32 total-order map: u32 max == float max.
__device__ __forceinline__ unsigned fmono(float v) {
    unsigned u = __float_as_uint(v);
    return ((int)u < 0) ? ~u : (u ^ 0x80000000u);
}
__device__ __forceinline__ float fmono_inv(unsigned k) {
    return __uint_as_float(((int)k < 0) ? (k ^ 0x80000000u) : ~k);
}

// L2 prefetch: no destination register, no ordering obligations.
__device__ __forceinline__ void prefetch_l2(const void* p) {
    asm volatile("prefetch.global.L2 [%0];" :: "l"(p));
}

// R10 kernel (33.5us) verbatim, plus depth-2 L2 prefetch: while registers
// hold chunk k+1, lanes 0/8/16/24 prefetch chunk k+2's cache lines into L2.
// LDGs for k+2 then hit L2 (~250cyc) instead of DRAM (~600cyc) with zero
// register/smem cost, preserving the 128-reg / 4-CTA equilibrium.
__global__ void __launch_bounds__(TPB, 4)
gating_kernel(const float* __restrict__ x, const float* __restrict__ W,
              const float* __restrict__ b, float* __restrict__ out_w,
              float* __restrict__ out_i, int write_idx)
{
    __shared__ float4 Ws[NEXP * 256];   // 8 x 1024 floats = 32 KB

    const int tid  = threadIdx.x;
    const int lane = tid & 31;
    const int wid  = tid >> 5;

    // Stage W: 2048 float4 / 128 threads = 16 each.
    {
        const float4* Wv = (const float4*)W;
#pragma unroll
        for (int i = 0; i < 16; i++)
            Ws[tid + i * TPB] = Wv[tid + i * TPB];
    }
    __syncthreads();   // the only block barrier in the kernel

    const int   elane = (lane >> 2) & 7;      // expert this lane ends up with
    const float bval  = b[elane];

    const int t0 = (blockIdx.x * WARPS + wid) * TPW;
    const float4* xp4 = (const float4*)x + (size_t)t0 * 256 + lane;
    // token (g*4+t), chunk c lives at xp4[(g*4+t)*256 + c*32]

    // Prologue: load group 0, chunk 0; prefetch chunk 1 lines to L2.
    float4 xn0 = xp4[0 * 256];
    float4 xn1 = xp4[1 * 256];
    float4 xn2 = xp4[2 * 256];
    float4 xn3 = xp4[3 * 256];
    if ((lane & 7) == 0)
        prefetch_l2(xp4 + (lane >> 3) * 256 + 32);

#pragma unroll 1
    for (int g = 0; g < NGRP; g++) {
        ull acc[NEXP][TPG];
#pragma unroll
        for (int e = 0; e < NEXP; e++)
#pragma unroll
            for (int t = 0; t < TPG; t++) acc[e][t] = 0ull;

        const int gbase = g * TPG * 256;

#pragma unroll
        for (int c = 0; c < 8; c++) {
            // Consume prefetched x into packed form (this is the stall point).
            ull xlo[TPG], xhi[TPG];
            xlo[0] = pack2(xn0.x, xn0.y); xhi[0] = pack2(xn0.z, xn0.w);
            xlo[1] = pack2(xn1.x, xn1.y); xhi[1] = pack2(xn1.z, xn1.w);
            xlo[2] = pack2(xn2.x, xn2.y); xhi[2] = pack2(xn2.z, xn2.w);
            xlo[3] = pack2(xn3.x, xn3.y); xhi[3] = pack2(xn3.z, xn3.w);

            // Prefetch next chunk into registers (or next group's chunk 0).
            if (c < 7) {
                const int o = gbase + (c + 1) * 32;
                xn0 = xp4[o + 0 * 256]; xn1 = xp4[o + 1 * 256];
                xn2 = xp4[o + 2 * 256]; xn3 = xp4[o + 3 * 256];
            } else if (g < NGRP - 1) {
                const int o = (g + 1) * TPG * 256;
                xn0 = xp4[o + 0 * 256]; xn1 = xp4[o + 1 * 256];
                xn2 = xp4[o + 2 * 256]; xn3 = xp4[o + 3 * 256];
            }

            // L2 prefetch for flat chunk k+2 (clamped). Lanes 0/8/16/24 each
            // cover one token; the prefetched line spans this lane-group's
            // 128-B slice of that token's 512-B chunk.
            {
                int kn = g * 8 + c + 2;
                kn = (kn < NCHUNK - 1) ? kn : (NCHUNK - 1);
                if ((lane & 7) == 0) {
                    const int off = ((kn >> 3) * (TPG * 256)) + ((kn & 7) * 32)
                                    + (lane >> 3) * 256;
                    prefetch_l2(xp4 + off);
                }
            }

            // W for this chunk, 4 experts at a time (keeps W regs transient).
            const int wbase = c * 32 + lane;
#pragma unroll
            for (int eb = 0; eb < NEXP; eb += 4) {
                float4 w0 = Ws[(eb + 0) * 256 + wbase];
                float4 w1 = Ws[(eb + 1) * 256 + wbase];
                float4 w2 = Ws[(eb + 2) * 256 + wbase];
                float4 w3 = Ws[(eb + 3) * 256 + wbase];
                ull wl0 = pack2(w0.x, w0.y), wh0 = pack2(w0.z, w0.w);
                ull wl1 = pack2(w1.x, w1.y), wh1 = pack2(w1.z, w1.w);
                ull wl2 = pack2(w2.x, w2.y), wh2 = pack2(w2.z, w2.w);
                ull wl3 = pack2(w3.x, w3.y), wh3 = pack2(w3.z, w3.w);
#pragma unroll
                for (int t = 0; t < TPG; t++) {
                    acc[eb + 0][t] = ffma2(xhi[t], wh0, ffma2(xlo[t], wl0, acc[eb + 0][t]));
                    acc[eb + 1][t] = ffma2(xhi[t], wh1, ffma2(xlo[t], wl1, acc[eb + 1][t]));
                    acc[eb + 2][t] = ffma2(xhi[t], wh2, ffma2(xlo[t], wl2, acc[eb + 2][t]));
                    acc[eb + 3][t] = ffma2(xhi[t], wh3, ffma2(xlo[t], wl3, acc[eb + 3][t]));
                }
            }
        }

        // Finalize + epilogue per token, fully in-warp (R10 verbatim).
#pragma unroll
        for (int t = 0; t < TPG; t++) {
            float s[NEXP];
#pragma unroll
            for (int e = 0; e < NEXP; e++) {
                float lo, hi; unpack2(acc[e][t], lo, hi);
                s[e] = lo + hi;
            }

            // 9-shfl butterfly: experts over lane bits 4,3,2; dims over 1,0.
            const bool h16 = (lane & 16) != 0;
#pragma unroll
            for (int v = 0; v < 4; v++) {
                float d = __shfl_xor_sync(~0u, h16 ? s[v] : s[v + 4], 16);
                s[v] = (h16 ? s[v + 4] : s[v]) + d;
            }
            const bool h8 = (lane & 8) != 0;
#pragma unroll
            for (int v = 0; v < 2; v++) {
                float d = __shfl_xor_sync(~0u, h8 ? s[v] : s[v + 2], 8);
                s[v] = (h8 ? s[v + 2] : s[v]) + d;
            }
            const bool h4 = (lane & 4) != 0;
            {
                float d = __shfl_xor_sync(~0u, h4 ? s[0] : s[1], 4);
                s[0] = (h4 ? s[1] : s[0]) + d;
            }
            float r = s[0];
            r += __shfl_xor_sync(~0u, r, 2);
            r += __shfl_xor_sync(~0u, r, 1);

            // Lane now holds the complete logit for expert `elane` (x4 copies).
            const float L = r + bval;
            const unsigned key = fmono(L);
            unsigned k1 = redux_max_u32(key);
            unsigned i1 = redux_min_u32((key == k1) ? (unsigned)elane : 0xFFu);
            unsigned key2 = ((unsigned)elane == i1) ? 0u : key;
            unsigned k2 = redux_max_u32(key2);
            unsigned i2 = redux_min_u32((key2 == k2) ? (unsigned)elane : 0xFFu);

            const float m1 = fmono_inv(k1);
            const float m2 = fmono_inv(k2);
            const float tt  = __expf(m2 - m1);     // m2 <= m1 -> (0,1]
            const float inv = 1.0f / (1.0f + tt);

            const int token = t0 + g * TPG + t;
            if ((lane & 3) == 0) {
                float wgt = ((unsigned)elane == i1) ? inv
                          : (((unsigned)elane == i2) ? tt * inv : 0.0f);
                out_w[token * 8 + elane] = wgt;
            }
            if (lane == t * 8 && write_idx)
                *(float2*)(out_i + token * 2) =
                    make_float2((float)i1, (float)i2);
        }
    }
}

extern "C" void kernel_launch(void* const* d_in, const int* in_sizes, int n_in,
                              void* d_out, int out_size)
{
    const float* x = nullptr; const float* W = nullptr; const float* b = nullptr;
    for (int i = 0; i < n_in; i++) {
        if (in_sizes[i] == NEXP)                b = (const float*)d_in[i];
        else if (in_sizes[i] == NEXP * DMODEL)  W = (const float*)d_in[i];
        else                                    x = (const float*)d_in[i];
    }

    float* ow = (float*)d_out;                       // weights: [B,S,E] f32
    float* oi = ow + (size_t)TOKENS_TOT * NEXP;      // indices (as f32): [B,S,2]
    const int need = TOKENS_TOT * NEXP + TOKENS_TOT * 2;
    const int write_idx = (out_size >= need) ? 1 : 0;

    gating_kernel<<<NBLOCKS, TPB>>>(x, W, b, ow, oi, write_idx);
}

// round 15
// speedup vs baseline: 2.4474x; 1.1725x over previous
#include <cuda_runtime.h>
#include <cstdint>

#define DMODEL     1024
#define NEXP       8
#define TOKENS_TOT 32768
#define TPB        128
#define WARPS      4            // per CTA
#define TPW        16           // tokens per warp
#define TPG        4            // tokens per group (inner batch)
#define NGRP       (TPW / TPG)  // 4
#define NCHUNK     (NGRP * 8)   // 32 flat chunks per warp
#define NBLOCKS    (TOKENS_TOT / (WARPS * TPW))   // 512

typedef unsigned long long ull;

// ---------- packed fp32x2 FMA (sm_103a) ----------
__device__ __forceinline__ ull ffma2(ull a, ull b, ull c) {
    ull d;
    asm("fma.rn.f32x2 %0, %1, %2, %3;" : "=l"(d) : "l"(a), "l"(b), "l"(c));
    return d;
}
__device__ __forceinline__ void unpack2(ull v, float& lo, float& hi) {
    asm("mov.b64 {%0, %1}, %2;" : "=f"(lo), "=f"(hi) : "l"(v));
}

// ---------- integer warp redux (f32 redux does NOT exist on sm_103) ----------
__device__ __forceinline__ unsigned redux_max_u32(unsigned v) {
    unsigned r;
    asm volatile("redux.sync.max.u32 %0, %1, 0xffffffff;" : "=r"(r) : "r"(v));
    return r;
}
__device__ __forceinline__ unsigned redux_min_u32(unsigned v) {
    unsigned r;
    asm volatile("redux.sync.min.u32 %0, %1, 0xffffffff;" : "=r"(r) : "r"(v));
    return r;
}

// Order-preserving float <-> u32 total-order map: u32 max == float max.
__device__ __forceinline__ unsigned fmono(float v) {
    unsigned u = __float_as_uint(v);
    return ((int)u < 0) ? ~u : (u ^ 0x80000000u);
}
__device__ __forceinline__ float fmono_inv(unsigned k) {
    return __uint_as_float(((int)k < 0) ? (k ^ 0x80000000u) : ~k);
}

// ---------- cp.async (LDGSTS): in-flight bytes without register cost ----------
__device__ __forceinline__ void cp_async16(uint32_t smem_dst, const void* gmem_src) {
    asm volatile("cp.async.cg.shared.global [%0], [%1], 16;"
                 :: "r"(smem_dst), "l"(gmem_src));
}
#define CP_COMMIT() asm volatile("cp.async.commit_group;" ::: "memory")
#define CP_WAIT1()  asm volatile("cp.async.wait_group 1;"  ::: "memory")

// R10 core (33.5us) with the x path moved to a per-warp cp.async double
// buffer: 2 chunks (4KB) per warp permanently in DRAM flight, held in the
// async queue + SMEM instead of registers. x and W consumed as ulonglong2
// (no packing movs). Same FFMA2 core, same in-warp redux epilogue, one
// block barrier total.
__global__ void __launch_bounds__(TPB, 4)
gating_kernel(const float* __restrict__ x, const float* __restrict__ W,
              const float* __restrict__ b, float* __restrict__ out_w,
              float* __restrict__ out_i, int write_idx)
{
    __shared__ ulonglong2 Ws[NEXP * 256];          // 32 KB
    __shared__ ulonglong2 ring[WARPS][2][TPG * 32]; // 16 KB (2KB/slot/warp)

    const int tid  = threadIdx.x;
    const int lane = tid & 31;
    const int wid  = tid >> 5;

    const int t0 = (blockIdx.x * WARPS + wid) * TPW;
    // byte address of this warp's token block; token tok, chunk c, lane l
    // -> gxb + tok*4096 + c*512 + l*16
    const char* gxb = (const char*)(x + (size_t)t0 * DMODEL);

    const uint32_t rbase =
        (uint32_t)__cvta_generic_to_shared(&ring[wid][0][0]);
    const uint32_t rlane = (uint32_t)lane * 16u;

    // Prologue: chunks 0 and 1 of group 0 in flight before the barrier.
#pragma unroll
    for (int k = 0; k < 2; k++) {
#pragma unroll
        for (int t = 0; t < TPG; t++)
            cp_async16(rbase + (uint32_t)(k & 1) * 2048u + (uint32_t)t * 512u + rlane,
                       gxb + (size_t)t * 4096 + (size_t)k * 512 + lane * 16);
        CP_COMMIT();
    }

    // Stage W: 2048 x 16B / 128 threads = 16 each.
    {
        const ulonglong2* Wv = (const ulonglong2*)W;
#pragma unroll
        for (int i = 0; i < 16; i++)
            Ws[tid + i * TPB] = Wv[tid + i * TPB];
    }
    __syncthreads();   // the only block barrier in the kernel

    const int   elane = (lane >> 2) & 7;      // expert this lane ends up with
    const float bval  = b[elane];

#pragma unroll 1
    for (int g = 0; g < NGRP; g++) {
        ull acc[NEXP][TPG];
#pragma unroll
        for (int e = 0; e < NEXP; e++)
#pragma unroll
            for (int t = 0; t < TPG; t++) acc[e][t] = 0ull;

#pragma unroll
        for (int c = 0; c < 8; c++) {
            const int k = g * 8 + c;

            // Chunk k has landed (only chunk k+1 may still be pending).
            CP_WAIT1();
            ull xlo[TPG], xhi[TPG];
            const ulonglong2* slotp = &ring[wid][k & 1][0];
#pragma unroll
            for (int t = 0; t < TPG; t++) {
                ulonglong2 v = slotp[t * 32 + lane];
                xlo[t] = v.x; xhi[t] = v.y;
            }

            // Refill the just-consumed slot with chunk k+2 (clamped; the
            // tail duplicates hit L2 and are never read).
            {
                int kp = k + 2;
                kp = (kp < NCHUNK - 1) ? kp : (NCHUNK - 1);
                const int gp = kp >> 3, cp = kp & 7;
#pragma unroll
                for (int t = 0; t < TPG; t++)
                    cp_async16(rbase + (uint32_t)(kp & 1) * 2048u + (uint32_t)t * 512u + rlane,
                               gxb + (size_t)(gp * TPG + t) * 4096 + (size_t)cp * 512 + lane * 16);
                CP_COMMIT();
            }

            // W for this chunk, 4 experts at a time (ulonglong2: no packing).
            const ulonglong2* wrow = Ws + c * 32 + lane;
#pragma unroll
            for (int eb = 0; eb < NEXP; eb += 4) {
                ulonglong2 w0 = wrow[(eb + 0) * 256];
                ulonglong2 w1 = wrow[(eb + 1) * 256];
                ulonglong2 w2 = wrow[(eb + 2) * 256];
                ulonglong2 w3 = wrow[(eb + 3) * 256];
#pragma unroll
                for (int t = 0; t < TPG; t++) {
                    acc[eb + 0][t] = ffma2(xhi[t], w0.y, ffma2(xlo[t], w0.x, acc[eb + 0][t]));
                    acc[eb + 1][t] = ffma2(xhi[t], w1.y, ffma2(xlo[t], w1.x, acc[eb + 1][t]));
                    acc[eb + 2][t] = ffma2(xhi[t], w2.y, ffma2(xlo[t], w2.x, acc[eb + 2][t]));
                    acc[eb + 3][t] = ffma2(xhi[t], w3.y, ffma2(xlo[t], w3.x, acc[eb + 3][t]));
                }
            }
        }

        // Finalize + epilogue per token, fully in-warp (R10 verbatim).
#pragma unroll
        for (int t = 0; t < TPG; t++) {
            float s[NEXP];
#pragma unroll
            for (int e = 0; e < NEXP; e++) {
                float lo, hi; unpack2(acc[e][t], lo, hi);
                s[e] = lo + hi;
            }

            // 9-shfl butterfly: experts over lane bits 4,3,2; dims over 1,0.
            const bool h16 = (lane & 16) != 0;
#pragma unroll
            for (int v = 0; v < 4; v++) {
                float d = __shfl_xor_sync(~0u, h16 ? s[v] : s[v + 4], 16);
                s[v] = (h16 ? s[v + 4] : s[v]) + d;
            }
            const bool h8 = (lane & 8) != 0;
#pragma unroll
            for (int v = 0; v < 2; v++) {
                float d = __shfl_xor_sync(~0u, h8 ? s[v] : s[v + 2], 8);
                s[v] = (h8 ? s[v + 2] : s[v]) + d;
            }
            const bool h4 = (lane & 4) != 0;
            {
                float d = __shfl_xor_sync(~0u, h4 ? s[0] : s[1], 4);
                s[0] = (h4 ? s[1] : s[0]) + d;
            }
            float r = s[0];
            r += __shfl_xor_sync(~0u, r, 2);
            r += __shfl_xor_sync(~0u, r, 1);

            // Lane holds the complete logit for expert `elane` (x4 copies).
            const float L = r + bval;
            const unsigned key = fmono(L);
            unsigned k1 = redux_max_u32(key);
            unsigned i1 = redux_min_u32((key == k1) ? (unsigned)elane : 0xFFu);
            unsigned key2 = ((unsigned)elane == i1) ? 0u : key;
            unsigned k2 = redux_max_u32(key2);
            unsigned i2 = redux_min_u32((key2 == k2) ? (unsigned)elane : 0xFFu);

            const float m1 = fmono_inv(k1);
            const float m2 = fmono_inv(k2);
            const float tt  = __expf(m2 - m1);     // m2 <= m1 -> (0,1]
            const float inv = 1.0f / (1.0f + tt);

            const int token = t0 + g * TPG + t;
            if ((lane & 3) == 0) {
                float wgt = ((unsigned)elane == i1) ? inv
                          : (((unsigned)elane == i2) ? tt * inv : 0.0f);
                out_w[token * 8 + elane] = wgt;
            }
            if (lane == t * 8 && write_idx)
                *(float2*)(out_i + token * 2) =
                    make_float2((float)i1, (float)i2);
        }
    }
}

extern "C" void kernel_launch(void* const* d_in, const int* in_sizes, int n_in,
                              void* d_out, int out_size)
{
    const float* x = nullptr; const float* W = nullptr; const float* b = nullptr;
    for (int i = 0; i < n_in; i++) {
        if (in_sizes[i] == NEXP)                b = (const float*)d_in[i];
        else if (in_sizes[i] == NEXP * DMODEL)  W = (const float*)d_in[i];
        else                                    x = (const float*)d_in[i];
    }

    float* ow = (float*)d_out;                       // weights: [B,S,E] f32
    float* oi = ow + (size_t)TOKENS_TOT * NEXP;      // indices (as f32): [B,S,2]
    const int need = TOKENS_TOT * NEXP + TOKENS_TOT * 2;
    const int write_idx = (out_size >= need) ? 1 : 0;

    gating_kernel<<<NBLOCKS, TPB>>>(x, W, b, ow, oi, write_idx);
}